// round 16
// baseline (speedup 1.0000x reference)
#include <cuda_runtime.h>
#include <cuda_bf16.h>
#include <cuda_fp16.h>
#include <cstdint>
#include <cstddef>

// ---------------- problem constants ----------------
#define NB 4
#define NT 4096
#define ND 1024
#define NH 16
#define NE 64
#define NBH (NB*NH)     // 64
#define NM (NB*NT)      // 16384
#define KK 1024         // plain fp16 K (all GEMMs)
#define SPLITR 8
#define TCH (NT/SPLITR) // 512

// ---------------- GEMM tiling: CTA 128x128, 4 warps, warp 64x64, 3 stages ---
#define BM 128
#define BN 128
#define A_TILE (BM*128)             // 16384
#define B_TILE (BN*128)             // 16384
#define STAGE_BYTES (A_TILE + B_TILE)   // 32768
#define STAGES 3
#define GEMM_SMEM (STAGES*STAGE_BYTES)  // 98304
#define NCH (KK/64)                 // 16
#define OSCL 65536.0f
#define IOSCL (1.0f/65536.0f)

// ---------------- scratch (device globals) ----------------
__device__ unsigned short g_Aq[(size_t)NM*KK];    // q fp16
__device__ unsigned short g_Akv[(size_t)NM*KK];   // kv fp16
__device__ unsigned short g_Azq[(size_t)NM*KK];   // A'' = 2^16*z*qh2 fp16
__device__ unsigned short g_Bq[(size_t)ND*KK];    // Wq fp16 [n][k]
__device__ unsigned short g_Bk[(size_t)ND*KK];    // Wk fp16 [n][k]
__device__ unsigned short g_Bv[(size_t)ND*KK];    // Wv fp16 [n][k]
__device__ unsigned short g_B2o[(size_t)NB*ND*KK];// B'' per batch fp16 [n][k]
__device__ unsigned short g_feat[2][(size_t)NBH*NT*NE]; // kh2, vh fp16 [b,h,t,e]
__device__ float g_kvpart[(size_t)NBH*SPLITR*NE*NE];
__device__ float g_kspart[(size_t)NBH*SPLITR*NE];
__device__ float g_kvsum[(size_t)NBH*NE*NE];
__device__ float g_ksum[(size_t)NBH*NE];

// ---------------- helpers ----------------
__device__ __forceinline__ uint32_t s2u(const void* p) {
    uint32_t a;
    asm("{ .reg .u64 t; cvta.to.shared.u64 t, %1; cvt.u32.u64 %0, t; }" : "=r"(a) : "l"(p));
    return a;
}
__device__ __forceinline__ uint32_t swz(uint32_t b) { return b ^ ((b >> 3) & 0x70); }

__device__ __forceinline__ void cpasync16(uint32_t dst, const void* src) {
    asm volatile("cp.async.cg.shared.global [%0], [%1], 16;" :: "r"(dst), "l"(src));
}
__device__ __forceinline__ void cp_commit() {
    asm volatile("cp.async.commit_group;" ::: "memory");
}
template<int N>
__device__ __forceinline__ void cp_wait() {
    asm volatile("cp.async.wait_group %0;" :: "n"(N) : "memory");
}
__device__ __forceinline__ void ldsm4(uint32_t* r, uint32_t addr) {
    asm volatile("ldmatrix.sync.aligned.m8n8.x4.shared.b16 {%0,%1,%2,%3}, [%4];"
                 : "=r"(r[0]), "=r"(r[1]), "=r"(r[2]), "=r"(r[3]) : "r"(addr));
}
__device__ __forceinline__ void ldsm4t(uint32_t* r, uint32_t addr) {
    asm volatile("ldmatrix.sync.aligned.m8n8.x4.trans.shared.b16 {%0,%1,%2,%3}, [%4];"
                 : "=r"(r[0]), "=r"(r[1]), "=r"(r[2]), "=r"(r[3]) : "r"(addr));
}
__device__ __forceinline__ void mma_fp16(float* c, const uint32_t* a, const uint32_t* b) {
    asm volatile(
        "mma.sync.aligned.m16n8k16.row.col.f32.f16.f16.f32 "
        "{%0,%1,%2,%3}, {%4,%5,%6,%7}, {%8,%9}, {%0,%1,%2,%3};"
        : "+f"(c[0]), "+f"(c[1]), "+f"(c[2]), "+f"(c[3])
        : "r"(a[0]), "r"(a[1]), "r"(a[2]), "r"(a[3]), "r"(b[0]), "r"(b[1]));
}
__device__ __forceinline__ uint32_t pack_f16(float a, float b) {   // ushort2(h(a), h(b))
    uint32_t r;
    asm("cvt.rn.f16x2.f32 %0, %1, %2;" : "=r"(r) : "f"(b), "f"(a));
    return r;
}

// ---------------- fused prep (kv split + weight preps), exact 1D grid -------
// blocks [0, 16384): kv split; [16384, 16384+12288): wprep (Wq, Wk, Wv)
#define SPLIT_BLKS 16384
#define WPREP_BLKS 4096
__global__ void prep_all(const float4* __restrict__ xkv,
                         const float* __restrict__ Wq, const float* __restrict__ Wk,
                         const float* __restrict__ Wv,
                         unsigned short* __restrict__ Akv,
                         unsigned short* __restrict__ Bq, unsigned short* __restrict__ Bk,
                         unsigned short* __restrict__ Bv)
{
    int bid = blockIdx.x;
    if (bid < SPLIT_BLKS) {
        int gi = bid * 256 + threadIdx.x;
        float4 v = xkv[gi];
        uint32_t p01 = pack_f16(v.x, v.y);
        uint32_t p23 = pack_f16(v.z, v.w);
        *(uint2*)(Akv + (size_t)gi * 4) = make_uint2(p01, p23);
    } else {
        int r = bid - SPLIT_BLKS;
        int which = r >> 12;                     // /4096
        int idx = (r & (WPREP_BLKS - 1)) * 256 + threadIdx.x;
        int n = idx >> 10, k = idx & 1023;
        const float* W = (which == 0) ? Wq : (which == 1) ? Wk : Wv;
        float v = W[((size_t)(n >> 6) * ND + k) * NE + (n & 63)];
        unsigned short h = __half_as_ushort(__float2half_rn(v));
        (((which == 0) ? Bq : (which == 1) ? Bk : Bv))[idx] = h;
    }
}

// ---------------- shared fp16 GEMM mainloop (4 warps, warp 64x64) -----------
__device__ __forceinline__ void gemm_mainloop(
    uint32_t sb, const unsigned short* __restrict__ A, const unsigned short* __restrict__ Bm,
    int m0, int n0, int tid, int lane, int wid, float acc[4][8][4])
{
    const int lrow = tid >> 3, lkc = tid & 7;    // lrow 0..15
    const int mw = (wid & 1) * 64, nw = (wid >> 1) * 64;
    const int arow = mw + (lane & 15);
    const int brow = nw + (lane & 7) + ((lane >> 4) & 1) * 8;

    #pragma unroll
    for (int s = 0; s < STAGES - 1; ++s) {
        uint32_t sA = sb + s * STAGE_BYTES, sB = sA + A_TILE;
        int k0 = s * 64;
        #pragma unroll
        for (int i = 0; i < 8; ++i) {
            int row = lrow + i * 16;
            uint32_t so = swz(row * 128 + lkc * 16);
            cpasync16(sA + so, A  + (size_t)(m0 + row) * KK + k0 + lkc * 8);
            cpasync16(sB + so, Bm + (size_t)(n0 + row) * KK + k0 + lkc * 8);
        }
        cp_commit();
    }
    for (int ch = 0; ch < NCH; ++ch) {
        cp_wait<STAGES - 2>();
        __syncthreads();
        int chn = ch + STAGES - 1;
        if (chn < NCH) {
            int sl = chn % STAGES;
            uint32_t sA = sb + sl * STAGE_BYTES, sB = sA + A_TILE;
            int k0 = chn * 64;
            #pragma unroll
            for (int i = 0; i < 8; ++i) {
                int row = lrow + i * 16;
                uint32_t so = swz(row * 128 + lkc * 16);
                cpasync16(sA + so, A  + (size_t)(m0 + row) * KK + k0 + lkc * 8);
                cpasync16(sB + so, Bm + (size_t)(n0 + row) * KK + k0 + lkc * 8);
            }
        }
        cp_commit();
        const int s = ch % STAGES;
        const uint32_t aBase = sb + s * STAGE_BYTES;
        const uint32_t bBase = aBase + A_TILE;
        #pragma unroll
        for (int k16 = 0; k16 < 4; ++k16) {
            uint32_t a[4][4], bf[4][4];
            const int acol = (k16 * 16 + (lane >> 4) * 8) * 2;
            const int bcol = (k16 * 16 + ((lane >> 3) & 1) * 8) * 2;
            #pragma unroll
            for (int mi = 0; mi < 4; ++mi)
                ldsm4(a[mi], aBase + swz((arow + mi * 16) * 128 + acol));
            #pragma unroll
            for (int nj = 0; nj < 4; ++nj)
                ldsm4(bf[nj], bBase + swz((brow + nj * 16) * 128 + bcol));
            #pragma unroll
            for (int mi = 0; mi < 4; ++mi)
                #pragma unroll
                for (int n8 = 0; n8 < 8; ++n8)
                    mma_fp16(acc[mi][n8], a[mi], &bf[n8 >> 1][(n8 & 1) * 2]);
        }
    }
}

// ---------------- K|V projection GEMM (z: 0=K squared, 1=V, >=2: q-split) ---
__global__ void __launch_bounds__(128, 2) gemm_kv(
    const unsigned short* __restrict__ Akv,
    const unsigned short* __restrict__ Bk, const unsigned short* __restrict__ Bv,
    const float* __restrict__ bk, const float* __restrict__ bv,
    unsigned short* __restrict__ fk, unsigned short* __restrict__ fv,
    const float4* __restrict__ xq, unsigned short* __restrict__ Aq)
{
    // q-split rider blocks: 16 z-slices x 1024 = 16384 blocks, 128 thr each,
    // 2 float4 per thread -> 4M float4 total (DRAM work hidden under GEMM).
    if (blockIdx.z >= 2) {
        int linear = ((blockIdx.z - 2) * 128 + blockIdx.y) * 8 + blockIdx.x; // 0..16383
        int gi = linear * 128 + threadIdx.x;
        #pragma unroll
        for (int rep = 0; rep < 2; ++rep) {
            int g2 = gi + rep * (SPLIT_BLKS * 128);
            float4 v = xq[g2];
            uint32_t p01 = pack_f16(v.x, v.y);
            uint32_t p23 = pack_f16(v.z, v.w);
            *(uint2*)(Aq + (size_t)g2 * 4) = make_uint2(p01, p23);
        }
        return;
    }

    extern __shared__ __align__(128) char smem[];
    const uint32_t sb = s2u(smem);
    const int tid = threadIdx.x, lane = tid & 31, wid = tid >> 5;
    const int m0 = blockIdx.y * BM, n0 = blockIdx.x * BN;
    const int which = blockIdx.z;
    const unsigned short* Bm = (which == 0) ? Bk : Bv;
    const float* bias = (which == 0) ? bk : bv;
    unsigned short* C = (which == 0) ? fk : fv;

    float acc[4][8][4];
    #pragma unroll
    for (int i = 0; i < 4; ++i)
        #pragma unroll
        for (int j = 0; j < 8; ++j)
            #pragma unroll
            for (int r = 0; r < 4; ++r) acc[i][j][r] = 0.f;

    gemm_mainloop(sb, Akv, Bm, m0, n0, tid, lane, wid, acc);

    const int g = lane >> 2, t2 = (lane & 3) * 2;
    const int mw = (wid & 1) * 64, nw = (wid >> 1) * 64;
    #pragma unroll
    for (int mi = 0; mi < 4; ++mi) {
        #pragma unroll
        for (int n8 = 0; n8 < 8; ++n8) {
            int col = n0 + nw + n8 * 8 + t2;
            float b0 = bias[col], b1 = bias[col + 1];
            int r0 = m0 + mw + mi * 16 + g;
            int r1 = r0 + 8;
            float v00 = acc[mi][n8][0] + b0, v01 = acc[mi][n8][1] + b1;
            float v10 = acc[mi][n8][2] + b0, v11 = acc[mi][n8][3] + b1;
            if (which == 0) { v00 *= v00; v01 *= v01; v10 *= v10; v11 *= v11; }
            int h = col >> 6, e = col & 63;
            int b_0 = r0 >> 12, t_0 = r0 & (NT - 1);
            int b_1 = r1 >> 12, t_1 = r1 & (NT - 1);
            *(uint32_t*)(C + ((((size_t)b_0 * NH + h) * NT + t_0) * NE + e)) = pack_f16(v00, v01);
            *(uint32_t*)(C + ((((size_t)b_1 * NH + h) * NT + t_1) * NE + e)) = pack_f16(v10, v11);
        }
    }
}

// ---------------- Q projection GEMM fused with z-scale -> A'' ---------------
__global__ void __launch_bounds__(128, 2) gemm_qfused(
    const unsigned short* __restrict__ Aq, const unsigned short* __restrict__ Bq,
    const float* __restrict__ bq, const float* __restrict__ kss,
    unsigned short* __restrict__ Azq)
{
    extern __shared__ __align__(128) char smem[];
    const uint32_t sb = s2u(smem);
    const int tid = threadIdx.x, lane = tid & 31, wid = tid >> 5;
    const int m0 = blockIdx.y * BM, n0 = blockIdx.x * BN;

    float acc[4][8][4];
    #pragma unroll
    for (int i = 0; i < 4; ++i)
        #pragma unroll
        for (int j = 0; j < 8; ++j)
            #pragma unroll
            for (int r = 0; r < 4; ++r) acc[i][j][r] = 0.f;

    gemm_mainloop(sb, Aq, Bq, m0, n0, tid, lane, wid, acc);

    const int g = lane >> 2, t2 = (lane & 3) * 2;
    const int mw = (wid & 1) * 64, nw = (wid >> 1) * 64;
    const int b = m0 >> 12;
    const int hloc = wid >> 1;                // 0 or 1 (head within CTA)
    const int h = (n0 >> 6) + hloc;           // global head
    const int bh = b * NH + h;

    float ks0[8], ks1[8];
    #pragma unroll
    for (int n8 = 0; n8 < 8; ++n8) {
        int colh = n8 * 8 + t2;
        ks0[n8] = kss[bh * NE + colh];
        ks1[n8] = kss[bh * NE + colh + 1];
    }

    float* zred = (float*)smem;               // 256 floats: [t_local 128][head_local 2]
    __syncthreads();
    zred[tid] = 0.f; zred[tid + 128] = 0.f;
    __syncthreads();

    float part[4][2];
    #pragma unroll
    for (int mi = 0; mi < 4; ++mi) { part[mi][0] = 0.f; part[mi][1] = 0.f; }
    #pragma unroll
    for (int mi = 0; mi < 4; ++mi) {
        #pragma unroll
        for (int n8 = 0; n8 < 8; ++n8) {
            int col = n0 + nw + n8 * 8 + t2;
            float b0 = bq[col], b1 = bq[col + 1];
            float q00 = acc[mi][n8][0] + b0; q00 *= q00;
            float q01 = acc[mi][n8][1] + b1; q01 *= q01;
            float q10 = acc[mi][n8][2] + b0; q10 *= q10;
            float q11 = acc[mi][n8][3] + b1; q11 *= q11;
            acc[mi][n8][0] = q00; acc[mi][n8][1] = q01;
            acc[mi][n8][2] = q10; acc[mi][n8][3] = q11;
            part[mi][0] += q00 * ks0[n8] + q01 * ks1[n8];
            part[mi][1] += q10 * ks0[n8] + q11 * ks1[n8];
        }
    }
    #pragma unroll
    for (int mi = 0; mi < 4; ++mi) {
        int tl0 = mw + mi * 16 + g;
        atomicAdd(&zred[tl0 * 2 + hloc], part[mi][0]);
        atomicAdd(&zred[(tl0 + 8) * 2 + hloc], part[mi][1]);
    }
    __syncthreads();

    #pragma unroll
    for (int mi = 0; mi < 4; ++mi) {
        int tl0 = mw + mi * 16 + g;
        float z0 = OSCL / (zred[tl0 * 2 + hloc] + 1e-6f);
        float z1 = OSCL / (zred[(tl0 + 8) * 2 + hloc] + 1e-6f);
        int r0 = m0 + tl0;
        #pragma unroll
        for (int n8 = 0; n8 < 8; ++n8) {
            int colh = n8 * 8 + t2;
            *(uint32_t*)(Azq + (size_t)r0 * KK + h * NE + colh) =
                pack_f16(acc[mi][n8][0] * z0, acc[mi][n8][1] * z0);
            *(uint32_t*)(Azq + (size_t)(r0 + 8) * KK + h * NE + colh) =
                pack_f16(acc[mi][n8][2] * z1, acc[mi][n8][3] * z1);
        }
    }
}

// ---------------- O GEMM: out = (A'' x B''_b)*2^-16 + bo ----------------
__global__ void __launch_bounds__(128, 2) gemm_o(
    const unsigned short* __restrict__ A2, const unsigned short* __restrict__ B2o,
    const float* __restrict__ bo, float* __restrict__ out)
{
    extern __shared__ __align__(128) char smem[];
    const uint32_t sb = s2u(smem);
    const int tid = threadIdx.x, lane = tid & 31, wid = tid >> 5;
    const int m0 = blockIdx.y * BM, n0 = blockIdx.x * BN;
    const unsigned short* Bm = B2o + (size_t)(m0 >> 12) * ND * KK;

    float acc[4][8][4];
    #pragma unroll
    for (int i = 0; i < 4; ++i)
        #pragma unroll
        for (int j = 0; j < 8; ++j)
            #pragma unroll
            for (int r = 0; r < 4; ++r) acc[i][j][r] = 0.f;

    gemm_mainloop(sb, A2, Bm, m0, n0, tid, lane, wid, acc);

    const int g = lane >> 2, t2 = (lane & 3) * 2;
    const int mw = (wid & 1) * 64, nw = (wid >> 1) * 64;
    #pragma unroll
    for (int mi = 0; mi < 4; ++mi) {
        #pragma unroll
        for (int n8 = 0; n8 < 8; ++n8) {
            int col = n0 + nw + n8 * 8 + t2;
            float b0 = bo[col], b1 = bo[col + 1];
            int r0 = m0 + mw + mi * 16 + g;
            int r1 = r0 + 8;
            float2 v0 = make_float2(acc[mi][n8][0] * IOSCL + b0, acc[mi][n8][1] * IOSCL + b1);
            float2 v1 = make_float2(acc[mi][n8][2] * IOSCL + b0, acc[mi][n8][3] * IOSCL + b1);
            *(float2*)(out + (size_t)r0 * ND + col) = v0;
            *(float2*)(out + (size_t)r1 * ND + col) = v1;
        }
    }
}

// ---------------- kv_sum & k_sum via tensor cores (ldmatrix.trans) ----------
__global__ void __launch_bounds__(128) kvsum_mma(
    const unsigned short* __restrict__ kh2, const unsigned short* __restrict__ vh,
    float* __restrict__ kvp, float* __restrict__ ksp)
{
    __shared__ __align__(128) unsigned char sm[2 * 16384];
    const uint32_t sb = s2u(sm);
    const int bh = blockIdx.x, sp = blockIdx.y;
    const unsigned short* kb = kh2 + ((size_t)bh * NT + (size_t)sp * TCH) * NE;
    const unsigned short* vb = vh  + ((size_t)bh * NT + (size_t)sp * TCH) * NE;
    const int tid = threadIdx.x, lane = tid & 31, wid = tid >> 5;
    const int dbase = wid * 16;

    float c[8][4];
    #pragma unroll
    for (int i = 0; i < 8; ++i)
        #pragma unroll
        for (int r = 0; r < 4; ++r) c[i][r] = 0.f;
    float co[4] = {0.f, 0.f, 0.f, 0.f};
    const uint32_t onesr[2] = {0x3C003C00u, 0x3C003C00u};

    const int akrow = (lane & 7) + ((lane >> 4) & 1) * 8;
    const int adcol = dbase + ((lane >> 3) & 1) * 8;
    const int bkrow = (lane & 7) + ((lane >> 3) & 1) * 8;
    const int bnadd = ((lane >> 4) & 1) * 8;

    #define KV_FILL(stage, t0) do {                                            \
        uint32_t base_ = sb + (stage) * 16384;                                  \
        _Pragma("unroll")                                                       \
        for (int j_ = 0; j_ < 4; ++j_) {                                        \
            int idx_ = tid + j_ * 128;                                          \
            int row_ = idx_ >> 3, seg_ = idx_ & 7;                              \
            uint32_t so_ = swz(row_ * 128 + seg_ * 16);                         \
            cpasync16(base_ + so_,        kb + (size_t)((t0) + row_) * NE + seg_ * 8); \
            cpasync16(base_ + 8192 + so_, vb + (size_t)((t0) + row_) * NE + seg_ * 8); \
        }                                                                        \
        cp_commit();                                                            \
    } while (0)

    KV_FILL(0, 0);
    for (int ch = 0; ch < TCH / 64; ++ch) {
        cp_wait<0>();
        __syncthreads();
        if (ch + 1 < TCH / 64) KV_FILL((ch + 1) & 1, (ch + 1) * 64);
        uint32_t kbase = sb + (ch & 1) * 16384;
        uint32_t vbase = kbase + 8192;
        #pragma unroll
        for (int k16 = 0; k16 < 4; ++k16) {
            int kl = k16 * 16;
            uint32_t a[4];
            ldsm4t(a, kbase + swz((kl + akrow) * 128 + adcol * 2));
            #pragma unroll
            for (int nb = 0; nb < 4; ++nb) {
                uint32_t bf[4];
                ldsm4t(bf, vbase + swz((kl + bkrow) * 128 + (nb * 16 + bnadd) * 2));
                mma_fp16(c[nb * 2],     a, bf);
                mma_fp16(c[nb * 2 + 1], a, bf + 2);
            }
            mma_fp16(co, a, onesr);
        }
        __syncthreads();
    }
    #undef KV_FILL

    const int g = lane >> 2, t2 = (lane & 3) * 2;
    float* outp = kvp + ((size_t)(bh * SPLITR + sp)) * NE * NE;
    #pragma unroll
    for (int nb2 = 0; nb2 < 8; ++nb2) {
        int ebase = (nb2 >> 1) * 16 + (nb2 & 1) * 8;
        *(float2*)&outp[(size_t)(dbase + g) * NE + ebase + t2] =
            make_float2(c[nb2][0], c[nb2][1]);
        *(float2*)&outp[(size_t)(dbase + g + 8) * NE + ebase + t2] =
            make_float2(c[nb2][2], c[nb2][3]);
    }
    if ((lane & 3) == 0) {
        float* kso = ksp + (size_t)(bh * SPLITR + sp) * NE;
        kso[dbase + g]     = co[0];
        kso[dbase + g + 8] = co[2];
    }
}

// ---------------- kvsum_reduce: one thread per output element ----------------
__global__ void __launch_bounds__(256) kvsum_reduce(
    const float* __restrict__ kvp, const float* __restrict__ ksp,
    float* __restrict__ kvs, float* __restrict__ kss)
{
    int gi = blockIdx.x * 256 + threadIdx.x;   // over NBH*4096 = 262144
    int bh = gi >> 12;
    int i = gi & 4095;
    float s = 0.f;
    #pragma unroll
    for (int sp = 0; sp < SPLITR; ++sp)
        s += kvp[((size_t)(bh * SPLITR + sp)) * NE * NE + i];
    kvs[(size_t)bh * NE * NE + i] = s;
    if (gi < NBH * NE) {
        int bh2 = gi >> 6, d = gi & 63;
        float t = 0.f;
        #pragma unroll
        for (int sp = 0; sp < SPLITR; ++sp)
            t += ksp[(size_t)(bh2 * SPLITR + sp) * NE + d];
        kss[(size_t)bh2 * NE + d] = t;
    }
}

// ---------------- B'' build ----------------
__global__ __launch_bounds__(256) void buildB(
    const float* __restrict__ Wo, const float* __restrict__ kvs,
    unsigned short* __restrict__ B2o)
{
    int bh = blockIdx.y;
    int b = bh >> 4, h = bh & 15;
    int n0 = blockIdx.x * 64;
    __shared__ float skv[64][64];
    __shared__ float swo[64][65];
    int tid = threadIdx.x;
    for (int i = tid; i < 4096; i += 256)
        ((float*)skv)[i] = kvs[(size_t)bh*4096 + i];
    for (int i = tid; i < 4096; i += 256) {
        int n = i >> 6, e = i & 63;
        swo[n][e] = Wo[(size_t)(n0 + n) * ND + h * 64 + e];
    }
    __syncthreads();
    int n = tid & 63;
    int d0 = (tid >> 6) * 16;
    float acc[16];
    #pragma unroll
    for (int j = 0; j < 16; ++j) acc[j] = 0.f;
    for (int e = 0; e < 64; ++e) {
        float w = swo[n][e];
        #pragma unroll
        for (int j = 0; j < 16; ++j)
            acc[j] += w * skv[d0 + j][e];
    }
    size_t base = (size_t)b * ND * KK + (size_t)(n0 + n) * KK + h * 64 + d0;
    uint32_t pk[8];
    #pragma unroll
    for (int j = 0; j < 8; ++j) pk[j] = pack_f16(acc[2*j], acc[2*j+1]);
    *(uint4*)(&B2o[base])     = *(uint4*)(pk);
    *(uint4*)(&B2o[base + 8]) = *(uint4*)(pk + 4);
}

// ---------------- launch ----------------
extern "C" void kernel_launch(void* const* d_in, const int* in_sizes, int n_in,
                              void* d_out, int out_size)
{
    const float* q  = (const float*)d_in[0];
    const float* kv = (const float*)d_in[1];
    const float* Wq = (const float*)d_in[2];
    const float* bq = (const float*)d_in[3];
    const float* Wk = (const float*)d_in[4];
    const float* bk = (const float*)d_in[5];
    const float* Wv = (const float*)d_in[6];
    const float* bv = (const float*)d_in[7];
    const float* Wo = (const float*)d_in[8];
    const float* bo = (const float*)d_in[9];
    float* out = (float*)d_out;

    unsigned short *Aq, *Akv, *Azq, *Bq, *Bk, *Bv, *B2o, *feat;
    float *kvp, *ksp, *kvs, *kss;
    cudaGetSymbolAddress((void**)&Aq,   g_Aq);
    cudaGetSymbolAddress((void**)&Akv,  g_Akv);
    cudaGetSymbolAddress((void**)&Azq,  g_Azq);
    cudaGetSymbolAddress((void**)&Bq,   g_Bq);
    cudaGetSymbolAddress((void**)&Bk,   g_Bk);
    cudaGetSymbolAddress((void**)&Bv,   g_Bv);
    cudaGetSymbolAddress((void**)&B2o,  g_B2o);
    cudaGetSymbolAddress((void**)&feat, g_feat);
    cudaGetSymbolAddress((void**)&kvp,  g_kvpart);
    cudaGetSymbolAddress((void**)&ksp,  g_kspart);
    cudaGetSymbolAddress((void**)&kvs,  g_kvsum);
    cudaGetSymbolAddress((void**)&kss,  g_ksum);

    unsigned short* fk = feat + 0*(size_t)NBH*NT*NE;
    unsigned short* fv = feat + 1*(size_t)NBH*NT*NE;

    cudaFuncSetAttribute((const void*)gemm_kv,     cudaFuncAttributeMaxDynamicSharedMemorySize, GEMM_SMEM);
    cudaFuncSetAttribute((const void*)gemm_qfused, cudaFuncAttributeMaxDynamicSharedMemorySize, GEMM_SMEM);
    cudaFuncSetAttribute((const void*)gemm_o,      cudaFuncAttributeMaxDynamicSharedMemorySize, GEMM_SMEM);

    // [0] prep: kv split + weight preps (q split deferred into gemm_kv launch)
    prep_all<<<SPLIT_BLKS + 3 * WPREP_BLKS, 256>>>(
        (const float4*)kv, Wq, Wk, Wv, Akv, Bq, Bk, Bv);
    // [1] K | V projection GEMMs + q-split rider blocks (z >= 2)
    {
        dim3 grid(ND / BN, NM / BM, 2 + 16);
        gemm_kv<<<grid, 128, GEMM_SMEM>>>(Akv, Bk, Bv, bk, bv, fk, fv,
                                          (const float4*)q, Aq);
    }
    // [2][3] kv_sum / k_sum
    {
        dim3 grid(NBH, SPLITR);
        kvsum_mma<<<grid, 128>>>(fk, fv, kvp, ksp);
        kvsum_reduce<<<NBH * NE * NE / 256, 256>>>(kvp, ksp, kvs, kss);
    }
    // [4] B''
    {
        dim3 grid(ND / 64, NBH);
        buildB<<<grid, 256>>>(Wo, kvs, B2o);
    }
    // [5] Q projection fused with z-scale -> A''
    {
        dim3 grid(ND / BN, NM / BM);
        gemm_qfused<<<grid, 128, GEMM_SMEM>>>(Aq, Bq, bq, kss, Azq);
    }
    // [6] output GEMM
    {
        dim3 grid(ND / BN, NM / BM);
        gemm_o<<<grid, 128, GEMM_SMEM>>>(Azq, B2o, bo, out);
    }
}

// round 17
// speedup vs baseline: 1.0623x; 1.0623x over previous
#include <cuda_runtime.h>
#include <cuda_bf16.h>
#include <cuda_fp16.h>
#include <cstdint>
#include <cstddef>

// ---------------- problem constants ----------------
#define NB 4
#define NT 4096
#define ND 1024
#define NH 16
#define NE 64
#define NBH (NB*NH)     // 64
#define NM (NB*NT)      // 16384
#define KK 1024         // plain fp16 K (all GEMMs)
#define SPLITR 8
#define TCH (NT/SPLITR) // 512

// ---------------- GEMM tiling: CTA 128x128, 4 warps, warp 64x64, 3 stages ---
#define BM 128
#define BN 128
#define A_TILE (BM*128)             // 16384
#define B_TILE (BN*128)             // 16384
#define STAGE_BYTES (A_TILE + B_TILE)   // 32768
#define STAGES 3
#define GEMM_SMEM (STAGES*STAGE_BYTES)  // 98304
#define NCH (KK/64)                 // 16
#define OSCL 65536.0f
#define IOSCL (1.0f/65536.0f)

// ---------------- scratch (device globals) ----------------
__device__ unsigned short g_Aq[(size_t)NM*KK];    // q fp16
__device__ unsigned short g_Akv[(size_t)NM*KK];   // kv fp16
__device__ unsigned short g_Azq[(size_t)NM*KK];   // A'' = 2^16*z*qh2 fp16
__device__ unsigned short g_Bq[(size_t)ND*KK];    // Wq fp16 [n][k]
__device__ unsigned short g_Bk[(size_t)ND*KK];    // Wk fp16 [n][k]
__device__ unsigned short g_Bv[(size_t)ND*KK];    // Wv fp16 [n][k]
__device__ unsigned short g_B2o[(size_t)NB*ND*KK];// B'' per batch fp16 [n][k]
__device__ unsigned short g_feat[2][(size_t)NBH*NT*NE]; // kh2, vh fp16 [b,h,t,e]
__device__ float g_kvpart[(size_t)NBH*SPLITR*NE*NE];
__device__ float g_kspart[(size_t)NBH*SPLITR*NE];
__device__ float g_kvsum[(size_t)NBH*NE*NE];
__device__ float g_ksum[(size_t)NBH*NE];

// ---------------- helpers ----------------
__device__ __forceinline__ uint32_t s2u(const void* p) {
    uint32_t a;
    asm("{ .reg .u64 t; cvta.to.shared.u64 t, %1; cvt.u32.u64 %0, t; }" : "=r"(a) : "l"(p));
    return a;
}
__device__ __forceinline__ uint32_t swz(uint32_t b) { return b ^ ((b >> 3) & 0x70); }

__device__ __forceinline__ void cpasync16(uint32_t dst, const void* src) {
    asm volatile("cp.async.cg.shared.global [%0], [%1], 16;" :: "r"(dst), "l"(src));
}
__device__ __forceinline__ void cp_commit() {
    asm volatile("cp.async.commit_group;" ::: "memory");
}
template<int N>
__device__ __forceinline__ void cp_wait() {
    asm volatile("cp.async.wait_group %0;" :: "n"(N) : "memory");
}
__device__ __forceinline__ void ldsm4(uint32_t* r, uint32_t addr) {
    asm volatile("ldmatrix.sync.aligned.m8n8.x4.shared.b16 {%0,%1,%2,%3}, [%4];"
                 : "=r"(r[0]), "=r"(r[1]), "=r"(r[2]), "=r"(r[3]) : "r"(addr));
}
__device__ __forceinline__ void ldsm4t(uint32_t* r, uint32_t addr) {
    asm volatile("ldmatrix.sync.aligned.m8n8.x4.trans.shared.b16 {%0,%1,%2,%3}, [%4];"
                 : "=r"(r[0]), "=r"(r[1]), "=r"(r[2]), "=r"(r[3]) : "r"(addr));
}
__device__ __forceinline__ void mma_fp16(float* c, const uint32_t* a, const uint32_t* b) {
    asm volatile(
        "mma.sync.aligned.m16n8k16.row.col.f32.f16.f16.f32 "
        "{%0,%1,%2,%3}, {%4,%5,%6,%7}, {%8,%9}, {%0,%1,%2,%3};"
        : "+f"(c[0]), "+f"(c[1]), "+f"(c[2]), "+f"(c[3])
        : "r"(a[0]), "r"(a[1]), "r"(a[2]), "r"(a[3]), "r"(b[0]), "r"(b[1]));
}
__device__ __forceinline__ uint32_t pack_f16(float a, float b) {   // ushort2(h(a), h(b))
    uint32_t r;
    asm("cvt.rn.f16x2.f32 %0, %1, %2;" : "=r"(r) : "f"(b), "f"(a));
    return r;
}

// ---------------- fused prep, exact 1D grid (no dead blocks) ----------------
// blocks [0, 32768): activation converts (q then kv), 16384 blocks each
// blocks [32768, 45056): weight preps (Wq, Wk, Wv), 4096 blocks each
#define SPLIT_BLKS 16384
#define WPREP_BLKS 4096
__global__ void prep_all(const float4* __restrict__ xq, const float4* __restrict__ xkv,
                         const float* __restrict__ Wq, const float* __restrict__ Wk,
                         const float* __restrict__ Wv,
                         unsigned short* __restrict__ Aq, unsigned short* __restrict__ Akv,
                         unsigned short* __restrict__ Bq, unsigned short* __restrict__ Bk,
                         unsigned short* __restrict__ Bv)
{
    int bid = blockIdx.x;
    if (bid < 2 * SPLIT_BLKS) {
        int which = bid >> 14;                   // /16384
        int gi = (bid & (SPLIT_BLKS - 1)) * 256 + threadIdx.x;
        const float4* x = (which == 0) ? xq : xkv;
        unsigned short* A = (which == 0) ? Aq : Akv;
        float4 v = x[gi];
        uint32_t p01 = pack_f16(v.x, v.y);
        uint32_t p23 = pack_f16(v.z, v.w);
        *(uint2*)(A + (size_t)gi * 4) = make_uint2(p01, p23);
    } else {
        int r = bid - 2 * SPLIT_BLKS;
        int which = r >> 12;                     // /4096
        int idx = (r & (WPREP_BLKS - 1)) * 256 + threadIdx.x;
        int n = idx >> 10, k = idx & 1023;
        const float* W = (which == 0) ? Wq : (which == 1) ? Wk : Wv;
        float v = W[((size_t)(n >> 6) * ND + k) * NE + (n & 63)];
        unsigned short h = __half_as_ushort(__float2half_rn(v));
        (((which == 0) ? Bq : (which == 1) ? Bk : Bv))[idx] = h;
    }
}

// ---------------- shared fp16 GEMM mainloop (4 warps, warp 64x64) -----------
__device__ __forceinline__ void gemm_mainloop(
    uint32_t sb, const unsigned short* __restrict__ A, const unsigned short* __restrict__ Bm,
    int m0, int n0, int tid, int lane, int wid, float acc[4][8][4])
{
    const int lrow = tid >> 3, lkc = tid & 7;    // lrow 0..15
    const int mw = (wid & 1) * 64, nw = (wid >> 1) * 64;
    const int arow = mw + (lane & 15);
    const int brow = nw + (lane & 7) + ((lane >> 4) & 1) * 8;

    #pragma unroll
    for (int s = 0; s < STAGES - 1; ++s) {
        uint32_t sA = sb + s * STAGE_BYTES, sB = sA + A_TILE;
        int k0 = s * 64;
        #pragma unroll
        for (int i = 0; i < 8; ++i) {
            int row = lrow + i * 16;
            uint32_t so = swz(row * 128 + lkc * 16);
            cpasync16(sA + so, A  + (size_t)(m0 + row) * KK + k0 + lkc * 8);
            cpasync16(sB + so, Bm + (size_t)(n0 + row) * KK + k0 + lkc * 8);
        }
        cp_commit();
    }
    for (int ch = 0; ch < NCH; ++ch) {
        cp_wait<STAGES - 2>();
        __syncthreads();
        int chn = ch + STAGES - 1;
        if (chn < NCH) {
            int sl = chn % STAGES;
            uint32_t sA = sb + sl * STAGE_BYTES, sB = sA + A_TILE;
            int k0 = chn * 64;
            #pragma unroll
            for (int i = 0; i < 8; ++i) {
                int row = lrow + i * 16;
                uint32_t so = swz(row * 128 + lkc * 16);
                cpasync16(sA + so, A  + (size_t)(m0 + row) * KK + k0 + lkc * 8);
                cpasync16(sB + so, Bm + (size_t)(n0 + row) * KK + k0 + lkc * 8);
            }
        }
        cp_commit();
        const int s = ch % STAGES;
        const uint32_t aBase = sb + s * STAGE_BYTES;
        const uint32_t bBase = aBase + A_TILE;
        #pragma unroll
        for (int k16 = 0; k16 < 4; ++k16) {
            uint32_t a[4][4], bf[4][4];
            const int acol = (k16 * 16 + (lane >> 4) * 8) * 2;
            const int bcol = (k16 * 16 + ((lane >> 3) & 1) * 8) * 2;
            #pragma unroll
            for (int mi = 0; mi < 4; ++mi)
                ldsm4(a[mi], aBase + swz((arow + mi * 16) * 128 + acol));
            #pragma unroll
            for (int nj = 0; nj < 4; ++nj)
                ldsm4(bf[nj], bBase + swz((brow + nj * 16) * 128 + bcol));
            #pragma unroll
            for (int mi = 0; mi < 4; ++mi)
                #pragma unroll
                for (int n8 = 0; n8 < 8; ++n8)
                    mma_fp16(acc[mi][n8], a[mi], &bf[n8 >> 1][(n8 & 1) * 2]);
        }
    }
}

// ---------------- K|V projection GEMM (blockIdx.z: 0=K squared, 1=V) --------
__global__ void __launch_bounds__(128, 2) gemm_kv(
    const unsigned short* __restrict__ Akv,
    const unsigned short* __restrict__ Bk, const unsigned short* __restrict__ Bv,
    const float* __restrict__ bk, const float* __restrict__ bv,
    unsigned short* __restrict__ fk, unsigned short* __restrict__ fv)
{
    extern __shared__ __align__(128) char smem[];
    const uint32_t sb = s2u(smem);
    const int tid = threadIdx.x, lane = tid & 31, wid = tid >> 5;
    const int m0 = blockIdx.y * BM, n0 = blockIdx.x * BN;
    const int which = blockIdx.z;
    const unsigned short* Bm = (which == 0) ? Bk : Bv;
    const float* bias = (which == 0) ? bk : bv;
    unsigned short* C = (which == 0) ? fk : fv;

    float acc[4][8][4];
    #pragma unroll
    for (int i = 0; i < 4; ++i)
        #pragma unroll
        for (int j = 0; j < 8; ++j)
            #pragma unroll
            for (int r = 0; r < 4; ++r) acc[i][j][r] = 0.f;

    gemm_mainloop(sb, Akv, Bm, m0, n0, tid, lane, wid, acc);

    const int g = lane >> 2, t2 = (lane & 3) * 2;
    const int mw = (wid & 1) * 64, nw = (wid >> 1) * 64;
    #pragma unroll
    for (int mi = 0; mi < 4; ++mi) {
        #pragma unroll
        for (int n8 = 0; n8 < 8; ++n8) {
            int col = n0 + nw + n8 * 8 + t2;
            float b0 = bias[col], b1 = bias[col + 1];
            int r0 = m0 + mw + mi * 16 + g;
            int r1 = r0 + 8;
            float v00 = acc[mi][n8][0] + b0, v01 = acc[mi][n8][1] + b1;
            float v10 = acc[mi][n8][2] + b0, v11 = acc[mi][n8][3] + b1;
            if (which == 0) { v00 *= v00; v01 *= v01; v10 *= v10; v11 *= v11; }
            int h = col >> 6, e = col & 63;
            int b_0 = r0 >> 12, t_0 = r0 & (NT - 1);
            int b_1 = r1 >> 12, t_1 = r1 & (NT - 1);
            *(uint32_t*)(C + ((((size_t)b_0 * NH + h) * NT + t_0) * NE + e)) = pack_f16(v00, v01);
            *(uint32_t*)(C + ((((size_t)b_1 * NH + h) * NT + t_1) * NE + e)) = pack_f16(v10, v11);
        }
    }
}

// ---------------- Q projection GEMM fused with z-scale -> A'' ---------------
__global__ void __launch_bounds__(128, 2) gemm_qfused(
    const unsigned short* __restrict__ Aq, const unsigned short* __restrict__ Bq,
    const float* __restrict__ bq, const float* __restrict__ kss,
    unsigned short* __restrict__ Azq)
{
    extern __shared__ __align__(128) char smem[];
    const uint32_t sb = s2u(smem);
    const int tid = threadIdx.x, lane = tid & 31, wid = tid >> 5;
    const int m0 = blockIdx.y * BM, n0 = blockIdx.x * BN;

    float acc[4][8][4];
    #pragma unroll
    for (int i = 0; i < 4; ++i)
        #pragma unroll
        for (int j = 0; j < 8; ++j)
            #pragma unroll
            for (int r = 0; r < 4; ++r) acc[i][j][r] = 0.f;

    gemm_mainloop(sb, Aq, Bq, m0, n0, tid, lane, wid, acc);

    const int g = lane >> 2, t2 = (lane & 3) * 2;
    const int mw = (wid & 1) * 64, nw = (wid >> 1) * 64;
    const int b = m0 >> 12;
    const int hloc = wid >> 1;                // 0 or 1 (head within CTA)
    const int h = (n0 >> 6) + hloc;           // global head
    const int bh = b * NH + h;

    float ks0[8], ks1[8];
    #pragma unroll
    for (int n8 = 0; n8 < 8; ++n8) {
        int colh = n8 * 8 + t2;
        ks0[n8] = kss[bh * NE + colh];
        ks1[n8] = kss[bh * NE + colh + 1];
    }

    float* zred = (float*)smem;               // 256 floats: [t_local 128][head_local 2]
    __syncthreads();
    zred[tid] = 0.f; zred[tid + 128] = 0.f;
    __syncthreads();

    float part[4][2];
    #pragma unroll
    for (int mi = 0; mi < 4; ++mi) { part[mi][0] = 0.f; part[mi][1] = 0.f; }
    #pragma unroll
    for (int mi = 0; mi < 4; ++mi) {
        #pragma unroll
        for (int n8 = 0; n8 < 8; ++n8) {
            int col = n0 + nw + n8 * 8 + t2;
            float b0 = bq[col], b1 = bq[col + 1];
            float q00 = acc[mi][n8][0] + b0; q00 *= q00;
            float q01 = acc[mi][n8][1] + b1; q01 *= q01;
            float q10 = acc[mi][n8][2] + b0; q10 *= q10;
            float q11 = acc[mi][n8][3] + b1; q11 *= q11;
            acc[mi][n8][0] = q00; acc[mi][n8][1] = q01;
            acc[mi][n8][2] = q10; acc[mi][n8][3] = q11;
            part[mi][0] += q00 * ks0[n8] + q01 * ks1[n8];
            part[mi][1] += q10 * ks0[n8] + q11 * ks1[n8];
        }
    }
    #pragma unroll
    for (int mi = 0; mi < 4; ++mi) {
        int tl0 = mw + mi * 16 + g;
        atomicAdd(&zred[tl0 * 2 + hloc], part[mi][0]);
        atomicAdd(&zred[(tl0 + 8) * 2 + hloc], part[mi][1]);
    }
    __syncthreads();

    #pragma unroll
    for (int mi = 0; mi < 4; ++mi) {
        int tl0 = mw + mi * 16 + g;
        float z0 = OSCL / (zred[tl0 * 2 + hloc] + 1e-6f);
        float z1 = OSCL / (zred[(tl0 + 8) * 2 + hloc] + 1e-6f);
        int r0 = m0 + tl0;
        #pragma unroll
        for (int n8 = 0; n8 < 8; ++n8) {
            int colh = n8 * 8 + t2;
            *(uint32_t*)(Azq + (size_t)r0 * KK + h * NE + colh) =
                pack_f16(acc[mi][n8][0] * z0, acc[mi][n8][1] * z0);
            *(uint32_t*)(Azq + (size_t)(r0 + 8) * KK + h * NE + colh) =
                pack_f16(acc[mi][n8][2] * z1, acc[mi][n8][3] * z1);
        }
    }
}

// ---------------- O GEMM: out = (A'' x B''_b)*2^-16 + bo ----------------
__global__ void __launch_bounds__(128, 2) gemm_o(
    const unsigned short* __restrict__ A2, const unsigned short* __restrict__ B2o,
    const float* __restrict__ bo, float* __restrict__ out)
{
    extern __shared__ __align__(128) char smem[];
    const uint32_t sb = s2u(smem);
    const int tid = threadIdx.x, lane = tid & 31, wid = tid >> 5;
    const int m0 = blockIdx.y * BM, n0 = blockIdx.x * BN;
    const unsigned short* Bm = B2o + (size_t)(m0 >> 12) * ND * KK;

    float acc[4][8][4];
    #pragma unroll
    for (int i = 0; i < 4; ++i)
        #pragma unroll
        for (int j = 0; j < 8; ++j)
            #pragma unroll
            for (int r = 0; r < 4; ++r) acc[i][j][r] = 0.f;

    gemm_mainloop(sb, A2, Bm, m0, n0, tid, lane, wid, acc);

    const int g = lane >> 2, t2 = (lane & 3) * 2;
    const int mw = (wid & 1) * 64, nw = (wid >> 1) * 64;
    #pragma unroll
    for (int mi = 0; mi < 4; ++mi) {
        #pragma unroll
        for (int n8 = 0; n8 < 8; ++n8) {
            int col = n0 + nw + n8 * 8 + t2;
            float b0 = bo[col], b1 = bo[col + 1];
            int r0 = m0 + mw + mi * 16 + g;
            int r1 = r0 + 8;
            float2 v0 = make_float2(acc[mi][n8][0] * IOSCL + b0, acc[mi][n8][1] * IOSCL + b1);
            float2 v1 = make_float2(acc[mi][n8][2] * IOSCL + b0, acc[mi][n8][3] * IOSCL + b1);
            *(float2*)(out + (size_t)r0 * ND + col) = v0;
            *(float2*)(out + (size_t)r1 * ND + col) = v1;
        }
    }
}

// ---------------- kv_sum & k_sum via tensor cores (ldmatrix.trans) ----------
__global__ void __launch_bounds__(128) kvsum_mma(
    const unsigned short* __restrict__ kh2, const unsigned short* __restrict__ vh,
    float* __restrict__ kvp, float* __restrict__ ksp)
{
    __shared__ __align__(128) unsigned char sm[2 * 16384];
    const uint32_t sb = s2u(sm);
    const int bh = blockIdx.x, sp = blockIdx.y;
    const unsigned short* kb = kh2 + ((size_t)bh * NT + (size_t)sp * TCH) * NE;
    const unsigned short* vb = vh  + ((size_t)bh * NT + (size_t)sp * TCH) * NE;
    const int tid = threadIdx.x, lane = tid & 31, wid = tid >> 5;
    const int dbase = wid * 16;

    float c[8][4];
    #pragma unroll
    for (int i = 0; i < 8; ++i)
        #pragma unroll
        for (int r = 0; r < 4; ++r) c[i][r] = 0.f;
    float co[4] = {0.f, 0.f, 0.f, 0.f};
    const uint32_t onesr[2] = {0x3C003C00u, 0x3C003C00u};

    const int akrow = (lane & 7) + ((lane >> 4) & 1) * 8;
    const int adcol = dbase + ((lane >> 3) & 1) * 8;
    const int bkrow = (lane & 7) + ((lane >> 3) & 1) * 8;
    const int bnadd = ((lane >> 4) & 1) * 8;

    #define KV_FILL(stage, t0) do {                                            \
        uint32_t base_ = sb + (stage) * 16384;                                  \
        _Pragma("unroll")                                                       \
        for (int j_ = 0; j_ < 4; ++j_) {                                        \
            int idx_ = tid + j_ * 128;                                          \
            int row_ = idx_ >> 3, seg_ = idx_ & 7;                              \
            uint32_t so_ = swz(row_ * 128 + seg_ * 16);                         \
            cpasync16(base_ + so_,        kb + (size_t)((t0) + row_) * NE + seg_ * 8); \
            cpasync16(base_ + 8192 + so_, vb + (size_t)((t0) + row_) * NE + seg_ * 8); \
        }                                                                        \
        cp_commit();                                                            \
    } while (0)

    KV_FILL(0, 0);
    for (int ch = 0; ch < TCH / 64; ++ch) {
        cp_wait<0>();
        __syncthreads();
        if (ch + 1 < TCH / 64) KV_FILL((ch + 1) & 1, (ch + 1) * 64);
        uint32_t kbase = sb + (ch & 1) * 16384;
        uint32_t vbase = kbase + 8192;
        #pragma unroll
        for (int k16 = 0; k16 < 4; ++k16) {
            int kl = k16 * 16;
            uint32_t a[4];
            ldsm4t(a, kbase + swz((kl + akrow) * 128 + adcol * 2));
            #pragma unroll
            for (int nb = 0; nb < 4; ++nb) {
                uint32_t bf[4];
                ldsm4t(bf, vbase + swz((kl + bkrow) * 128 + (nb * 16 + bnadd) * 2));
                mma_fp16(c[nb * 2],     a, bf);
                mma_fp16(c[nb * 2 + 1], a, bf + 2);
            }
            mma_fp16(co, a, onesr);
        }
        __syncthreads();
    }
    #undef KV_FILL

    const int g = lane >> 2, t2 = (lane & 3) * 2;
    float* outp = kvp + ((size_t)(bh * SPLITR + sp)) * NE * NE;
    #pragma unroll
    for (int nb2 = 0; nb2 < 8; ++nb2) {
        int ebase = (nb2 >> 1) * 16 + (nb2 & 1) * 8;
        *(float2*)&outp[(size_t)(dbase + g) * NE + ebase + t2] =
            make_float2(c[nb2][0], c[nb2][1]);
        *(float2*)&outp[(size_t)(dbase + g + 8) * NE + ebase + t2] =
            make_float2(c[nb2][2], c[nb2][3]);
    }
    if ((lane & 3) == 0) {
        float* kso = ksp + (size_t)(bh * SPLITR + sp) * NE;
        kso[dbase + g]     = co[0];
        kso[dbase + g + 8] = co[2];
    }
}

// ---------------- kvsum_reduce: one thread per output element ----------------
__global__ void __launch_bounds__(256) kvsum_reduce(
    const float* __restrict__ kvp, const float* __restrict__ ksp,
    float* __restrict__ kvs, float* __restrict__ kss)
{
    int gi = blockIdx.x * 256 + threadIdx.x;   // over NBH*4096 = 262144
    int bh = gi >> 12;
    int i = gi & 4095;
    float s = 0.f;
    #pragma unroll
    for (int sp = 0; sp < SPLITR; ++sp)
        s += kvp[((size_t)(bh * SPLITR + sp)) * NE * NE + i];
    kvs[(size_t)bh * NE * NE + i] = s;
    if (gi < NBH * NE) {
        int bh2 = gi >> 6, d = gi & 63;
        float t = 0.f;
        #pragma unroll
        for (int sp = 0; sp < SPLITR; ++sp)
            t += ksp[(size_t)(bh2 * SPLITR + sp) * NE + d];
        kss[(size_t)bh2 * NE + d] = t;
    }
}

// ---------------- B'' build ----------------
__global__ __launch_bounds__(256) void buildB(
    const float* __restrict__ Wo, const float* __restrict__ kvs,
    unsigned short* __restrict__ B2o)
{
    int bh = blockIdx.y;
    int b = bh >> 4, h = bh & 15;
    int n0 = blockIdx.x * 64;
    __shared__ float skv[64][64];
    __shared__ float swo[64][65];
    int tid = threadIdx.x;
    for (int i = tid; i < 4096; i += 256)
        ((float*)skv)[i] = kvs[(size_t)bh*4096 + i];
    for (int i = tid; i < 4096; i += 256) {
        int n = i >> 6, e = i & 63;
        swo[n][e] = Wo[(size_t)(n0 + n) * ND + h * 64 + e];
    }
    __syncthreads();
    int n = tid & 63;
    int d0 = (tid >> 6) * 16;
    float acc[16];
    #pragma unroll
    for (int j = 0; j < 16; ++j) acc[j] = 0.f;
    for (int e = 0; e < 64; ++e) {
        float w = swo[n][e];
        #pragma unroll
        for (int j = 0; j < 16; ++j)
            acc[j] += w * skv[d0 + j][e];
    }
    size_t base = (size_t)b * ND * KK + (size_t)(n0 + n) * KK + h * 64 + d0;
    uint32_t pk[8];
    #pragma unroll
    for (int j = 0; j < 8; ++j) pk[j] = pack_f16(acc[2*j], acc[2*j+1]);
    *(uint4*)(&B2o[base])     = *(uint4*)(pk);
    *(uint4*)(&B2o[base + 8]) = *(uint4*)(pk + 4);
}

// ---------------- launch ----------------
extern "C" void kernel_launch(void* const* d_in, const int* in_sizes, int n_in,
                              void* d_out, int out_size)
{
    const float* q  = (const float*)d_in[0];
    const float* kv = (const float*)d_in[1];
    const float* Wq = (const float*)d_in[2];
    const float* bq = (const float*)d_in[3];
    const float* Wk = (const float*)d_in[4];
    const float* bk = (const float*)d_in[5];
    const float* Wv = (const float*)d_in[6];
    const float* bv = (const float*)d_in[7];
    const float* Wo = (const float*)d_in[8];
    const float* bo = (const float*)d_in[9];
    float* out = (float*)d_out;

    unsigned short *Aq, *Akv, *Azq, *Bq, *Bk, *Bv, *B2o, *feat;
    float *kvp, *ksp, *kvs, *kss;
    cudaGetSymbolAddress((void**)&Aq,   g_Aq);
    cudaGetSymbolAddress((void**)&Akv,  g_Akv);
    cudaGetSymbolAddress((void**)&Azq,  g_Azq);
    cudaGetSymbolAddress((void**)&Bq,   g_Bq);
    cudaGetSymbolAddress((void**)&Bk,   g_Bk);
    cudaGetSymbolAddress((void**)&Bv,   g_Bv);
    cudaGetSymbolAddress((void**)&B2o,  g_B2o);
    cudaGetSymbolAddress((void**)&feat, g_feat);
    cudaGetSymbolAddress((void**)&kvp,  g_kvpart);
    cudaGetSymbolAddress((void**)&ksp,  g_kspart);
    cudaGetSymbolAddress((void**)&kvs,  g_kvsum);
    cudaGetSymbolAddress((void**)&kss,  g_ksum);

    unsigned short* fk = feat + 0*(size_t)NBH*NT*NE;
    unsigned short* fv = feat + 1*(size_t)NBH*NT*NE;

    cudaFuncSetAttribute((const void*)gemm_kv,     cudaFuncAttributeMaxDynamicSharedMemorySize, GEMM_SMEM);
    cudaFuncSetAttribute((const void*)gemm_qfused, cudaFuncAttributeMaxDynamicSharedMemorySize, GEMM_SMEM);
    cudaFuncSetAttribute((const void*)gemm_o,      cudaFuncAttributeMaxDynamicSharedMemorySize, GEMM_SMEM);

    // [0] fused prep, exact grid: 32768 split blocks + 12288 wprep blocks
    prep_all<<<2 * SPLIT_BLKS + 3 * WPREP_BLKS, 256>>>(
        (const float4*)q, (const float4*)kv, Wq, Wk, Wv, Aq, Akv, Bq, Bk, Bv);
    // [1] K | V projection GEMMs -> fp16 feat
    {
        dim3 grid(ND / BN, NM / BM, 2);
        gemm_kv<<<grid, 128, GEMM_SMEM>>>(Akv, Bk, Bv, bk, bv, fk, fv);
    }
    // [2][3] kv_sum / k_sum
    {
        dim3 grid(NBH, SPLITR);
        kvsum_mma<<<grid, 128>>>(fk, fv, kvp, ksp);
        kvsum_reduce<<<NBH * NE * NE / 256, 256>>>(kvp, ksp, kvs, kss);
    }
    // [4] B''
    {
        dim3 grid(ND / 64, NBH);
        buildB<<<grid, 256>>>(Wo, kvs, B2o);
    }
    // [5] Q projection fused with z-scale -> A''
    {
        dim3 grid(ND / BN, NM / BM);
        gemm_qfused<<<grid, 128, GEMM_SMEM>>>(Aq, Bq, bq, kss, Azq);
    }
    // [6] output GEMM
    {
        dim3 grid(ND / BN, NM / BM);
        gemm_o<<<grid, 128, GEMM_SMEM>>>(Azq, B2o, bo, out);
    }
}